// round 8
// baseline (speedup 1.0000x reference)
#include <cuda_runtime.h>
#include <math.h>

#define NN   100000
#define EE   500000
#define TT   8
#define MSGD 64
#define HIDD 64
#define CC   16

typedef unsigned long long ull;

// ---------------------------------------------------------------------------
// Device scratch
// ---------------------------------------------------------------------------
__device__ __align__(16) float g_reduced[(size_t)NN * MSGD];
__device__ int g_counts[TT];
__device__ int g_cursor[TT];
__device__ int g_src_s[EE];
__device__ int g_dst_s[EE];

// ---------------------------------------------------------------------------
// Packed fp32x2 helpers (Blackwell FFMA2)
// ---------------------------------------------------------------------------
__device__ __forceinline__ void fma2(ull& d, ull a, ull b) {
    asm volatile("fma.rn.f32x2 %0, %1, %2, %0;" : "+l"(d) : "l"(a), "l"(b));
}
__device__ __forceinline__ float2 asf2(ull v) {
    float2 r;
    asm("mov.b64 {%0, %1}, %2;" : "=f"(r.x), "=f"(r.y) : "l"(v));
    return r;
}
// Fast gate math (err ~1e-6, budget 1e-3). Saturates correctly at +/-inf.
__device__ __forceinline__ float fast_sigmoid(float x) {
    return __fdividef(1.f, 1.f + __expf(-x));
}
__device__ __forceinline__ float fast_tanh(float x) {
    return 1.f - __fdividef(2.f, __expf(2.f * x) + 1.f);
}

// ---------------------------------------------------------------------------
// Kernel 0: zero reduction buffer + reset counters (separate launch from
// histogram adds — launch boundary is the grid-wide ordering point).
// ---------------------------------------------------------------------------
__global__ void zero_kernel() {
    int i = blockIdx.x * blockDim.x + threadIdx.x;
    if (i < NN * MSGD / 4) {
        reinterpret_cast<float4*>(g_reduced)[i] = make_float4(0.f, 0.f, 0.f, 0.f);
    }
    if (blockIdx.x == 0 && threadIdx.x < TT) {
        g_counts[threadIdx.x] = 0;
        g_cursor[threadIdx.x] = 0;
    }
}

// ---------------------------------------------------------------------------
// Kernel 1: per-block histogram of edge types
// ---------------------------------------------------------------------------
__global__ void hist_kernel(const int* __restrict__ etype) {
    __shared__ int h[TT];
    if (threadIdx.x < TT) h[threadIdx.x] = 0;
    __syncthreads();
    int e = blockIdx.x * blockDim.x + threadIdx.x;
    if (e < EE) atomicAdd(&h[etype[e]], 1);
    __syncthreads();
    if (threadIdx.x < TT) atomicAdd(&g_counts[threadIdx.x], h[threadIdx.x]);
}

// ---------------------------------------------------------------------------
// Kernel 2: bin edges by type (bases from final g_counts via local prefix)
// ---------------------------------------------------------------------------
__global__ void scatter_kernel(const int* __restrict__ etype,
                               const int* __restrict__ src,
                               const int* __restrict__ dst) {
    __shared__ int h[TT], base[TT], h2[TT];
    int e = blockIdx.x * blockDim.x + threadIdx.x;
    if (threadIdx.x < TT) { h[threadIdx.x] = 0; h2[threadIdx.x] = 0; }
    __syncthreads();
    int t = 0, s = 0, d = 0;
    bool valid = (e < EE);
    if (valid) {
        t = etype[e]; s = src[e]; d = dst[e];
        atomicAdd(&h[t], 1);
    }
    __syncthreads();
    if (threadIdx.x < TT) {
        int b = 0;
#pragma unroll
        for (int q = 0; q < TT; q++) {
            int c = g_counts[q];
            if (q < (int)threadIdx.x) b += c;
        }
        base[threadIdx.x] = b + atomicAdd(&g_cursor[threadIdx.x], h[threadIdx.x]);
    }
    __syncthreads();
    if (valid) {
        int pos = base[t] + atomicAdd(&h2[t], 1);
        g_src_s[pos] = s;
        g_dst_s[pos] = d;
    }
}

// ---------------------------------------------------------------------------
// Kernel 3: edge messages — K-SPLIT warp pairs.
// Warp pair shares an edge range. Even warp: feature dims [0,32); odd warp:
// [32,64). Each warp holds 2 weight rows x 32 cols per lane (64 regs), fetches
// only its half of each feature vector, computes partial dots for ALL 64
// output dims, and scatters partials with its own red.v4 (atomics combine the
// halves for free — no inter-warp sync). Total LDS/FFMA2/cp.async per edge
// unchanged vs R4; REDG data doubles. ~100 regs -> 2 CTAs/SM = 16 warps.
// ---------------------------------------------------------------------------
#define EBLOCKS  296
#define ETHREADS 256
#define NPAIRS   (EBLOCKS * (ETHREADS / 64))           // 1184
#define ECHUNK   ((EE + NPAIRS - 1) / NPAIRS)          // 423

__global__ void __launch_bounds__(ETHREADS, 2)
edge_kernel(const float* __restrict__ features,
            const float* __restrict__ edge_emb) {
    __shared__ float4 sf[ETHREADS / 32][8][8];   // [warp][slot][32 floats] = 8KB
    const unsigned FULL = 0xffffffffu;
    const int wib = threadIdx.x >> 5, lane = threadIdx.x & 31;

    int gw = blockIdx.x * (ETHREADS / 32) + wib;
    int pair = gw >> 1;
    int half = gw & 1;                            // which 32 feature dims

    long e0 = (long)pair * ECHUNK;
    if (e0 >= EE) return;
    long e1 = e0 + ECHUNK;
    if (e1 > EE) e1 = EE;

    int bases[TT + 1];
    {
        int b = 0;
#pragma unroll
        for (int t = 0; t < TT; t++) { bases[t] = b; b += g_counts[t]; }
        bases[TT] = b;
    }

    // Weights: rows 2*lane, 2*lane+1, cols [half*32, half*32+32) -> 64 floats
    ull wA[16], wB[16];
    long e = e0;
    int t = 0;
    while (e < e1) {
        while (bases[t + 1] <= e) t++;
        long seg_end = bases[t + 1] < e1 ? bases[t + 1] : e1;

        {
            const ulonglong2* pA = reinterpret_cast<const ulonglong2*>(
                edge_emb + (size_t)t * 4096 + (size_t)(2 * lane) * 64 + half * 32);
            const ulonglong2* pB = reinterpret_cast<const ulonglong2*>(
                edge_emb + (size_t)t * 4096 + (size_t)(2 * lane + 1) * 64 + half * 32);
#pragma unroll
            for (int q = 0; q < 8; q++) {
                ulonglong2 a = pA[q]; wA[2 * q] = a.x; wA[2 * q + 1] = a.y;
            }
#pragma unroll
            for (int q = 0; q < 8; q++) {
                ulonglong2 b = pB[q]; wB[2 * q] = b.x; wB[2 * q + 1] = b.y;
            }
        }

        for (long b0 = e; b0 < seg_end; b0 += 32) {
            int nb = (int)((seg_end - b0 < 32) ? (seg_end - b0) : 32);
            int my_s = 0, my_d = 0;
            if (lane < nb) {
                my_s = g_src_s[b0 + lane];
                my_d = g_dst_s[b0 + lane];
            }
            // Prologue: prefetch this warp's half of edges 0..5 (128B each)
#pragma unroll
            for (int j = 0; j < 6; j++) {
                if (j < nb) {
                    int s = __shfl_sync(FULL, my_s, j);
                    if (lane < 8) {
                        unsigned sp = (unsigned)__cvta_generic_to_shared(
                            &sf[wib][j & 7][lane]);
                        asm volatile("cp.async.cg.shared.global [%0], [%1], 16;"
                                     :: "r"(sp),
                                        "l"(features + (size_t)s * 64 + half * 32 + lane * 4));
                    }
                }
                asm volatile("cp.async.commit_group;");
            }
            for (int j = 0; j < nb; j++) {
                asm volatile("cp.async.wait_group 5;");
                __syncwarp();
                if (j + 6 < nb) {
                    int s = __shfl_sync(FULL, my_s, j + 6);
                    if (lane < 8) {
                        unsigned sp = (unsigned)__cvta_generic_to_shared(
                            &sf[wib][(j + 6) & 7][lane]);
                        asm volatile("cp.async.cg.shared.global [%0], [%1], 16;"
                                     :: "r"(sp),
                                        "l"(features + (size_t)s * 64 + half * 32 + lane * 4));
                    }
                }
                asm volatile("cp.async.commit_group;");

                int d = __shfl_sync(FULL, my_d, j);
                const ulonglong2* fp = reinterpret_cast<const ulonglong2*>(
                    &sf[wib][j & 7][0]);
                // 4 independent chains of depth 8
                ull a0 = 0, a1 = 0, b0v = 0, b1v = 0;
#pragma unroll
                for (int q = 0; q < 8; q += 2) {
                    ulonglong2 f0 = fp[q], f1 = fp[q + 1];
                    fma2(a0,  wA[2 * q],     f0.x); fma2(a0,  wA[2 * q + 1], f0.y);
                    fma2(a1,  wB[2 * q],     f0.x); fma2(a1,  wB[2 * q + 1], f0.y);
                    fma2(b0v, wA[2 * q + 2], f1.x); fma2(b0v, wA[2 * q + 3], f1.y);
                    fma2(b1v, wB[2 * q + 2], f1.x); fma2(b1v, wB[2 * q + 3], f1.y);
                }
                float2 A0 = asf2(a0), B0 = asf2(b0v);
                float2 A1 = asf2(a1), B1 = asf2(b1v);
                float r0 = (A0.x + A0.y) + (B0.x + B0.y);   // partial, dim 2*lane
                float r1 = (A1.x + A1.y) + (B1.x + B1.y);   // partial, dim 2*lane+1
                float p0 = __shfl_xor_sync(FULL, r0, 1);
                float p1 = __shfl_xor_sync(FULL, r1, 1);
                if (!(lane & 1)) {
                    const float* op = g_reduced + (size_t)d * 64 + 2 * lane;
                    asm volatile("red.global.add.v4.f32 [%0], {%1, %2, %3, %4};"
                                 :: "l"(op), "f"(r0), "f"(r1), "f"(p0), "f"(p1)
                                 : "memory");
                }
            }
            asm volatile("cp.async.wait_group 0;");
            __syncwarp();
        }
        e = seg_end;
    }
}

// ---------------------------------------------------------------------------
// Kernel 4: fused GRU + out projection (single-node body, fast gates).
// __launch_bounds__(256,2) caps regs at 128 -> 2 CTAs/SM (208KB smem) = 16
// warps. Contiguous per-block node ranges keep the tail balanced.
// ---------------------------------------------------------------------------
#define NODE_SMEM (26000 * 4)
#define NBLOCKS 296
#define NTHREADS 256
#define NODES_PER_BLOCK ((NN + NBLOCKS - 1) / NBLOCKS)   // 338

__global__ void __launch_bounds__(NTHREADS, 2)
node_kernel(const float* __restrict__ features,
            const float* __restrict__ W_ih, const float* __restrict__ W_hh,
            const float* __restrict__ b_ih, const float* __restrict__ b_hh,
            const float* __restrict__ W_out, const float* __restrict__ b_out,
            float* __restrict__ out) {
    extern __shared__ float sm[];
    float* sWih  = sm;            // 12288
    float* sWhh  = sm + 12288;    // 12288
    float* sWoT  = sm + 24576;    // 1024 (W_out transposed [64][16])
    float* sbih  = sm + 25600;    // 192
    float* sbhh  = sm + 25792;    // 192
    float* sbout = sm + 25984;    // 16

    {
        float4* d1 = reinterpret_cast<float4*>(sWih);
        const float4* s1 = reinterpret_cast<const float4*>(W_ih);
        for (int i = threadIdx.x; i < 3072; i += blockDim.x) d1[i] = s1[i];
        float4* d2 = reinterpret_cast<float4*>(sWhh);
        const float4* s2 = reinterpret_cast<const float4*>(W_hh);
        for (int i = threadIdx.x; i < 3072; i += blockDim.x) d2[i] = s2[i];
        for (int i = threadIdx.x; i < CC * 64; i += blockDim.x) {
            int c = i / 64, j = i % 64;
            sWoT[j * CC + c] = W_out[i];
        }
        for (int i = threadIdx.x; i < 192; i += blockDim.x) {
            sbih[i] = b_ih[i];
            sbhh[i] = b_hh[i];
        }
        if (threadIdx.x < CC) sbout[threadIdx.x] = b_out[threadIdx.x];
    }
    __syncthreads();

    int nstart = blockIdx.x * NODES_PER_BLOCK;
    int nend   = nstart + NODES_PER_BLOCK;
    if (nend > NN) nend = NN;

    for (int n = nstart + threadIdx.x; n < nend; n += NTHREADS) {

        ulonglong2 hh[16], rr[16];
        const ulonglong2* hp = reinterpret_cast<const ulonglong2*>(features + (size_t)n * 64);
        const ulonglong2* rp = reinterpret_cast<const ulonglong2*>(g_reduced + (size_t)n * 64);
#pragma unroll
        for (int q = 0; q < 16; q++) { hh[q] = hp[q]; rr[q] = rp[q]; }

        ull oacc[8];
        const ulonglong2* bo = reinterpret_cast<const ulonglong2*>(sbout);
#pragma unroll
        for (int i = 0; i < 4; i++) {
            ulonglong2 v = bo[i];
            oacc[2 * i] = v.x; oacc[2 * i + 1] = v.y;
        }

#pragma unroll 1
        for (int jq = 0; jq < 16; jq++) {
#pragma unroll
            for (int dj = 0; dj < 4; dj++) {
                int j = jq * 4 + dj;
                ull air = 0, aiz = 0, ain = 0, ahr = 0, ahz = 0, ahn = 0;
                const ulonglong2* wir = reinterpret_cast<const ulonglong2*>(sWih + (j      ) * 64);
                const ulonglong2* wiz = reinterpret_cast<const ulonglong2*>(sWih + (64  + j) * 64);
                const ulonglong2* win = reinterpret_cast<const ulonglong2*>(sWih + (128 + j) * 64);
                const ulonglong2* whr = reinterpret_cast<const ulonglong2*>(sWhh + (j      ) * 64);
                const ulonglong2* whz = reinterpret_cast<const ulonglong2*>(sWhh + (64  + j) * 64);
                const ulonglong2* whn = reinterpret_cast<const ulonglong2*>(sWhh + (128 + j) * 64);
#pragma unroll
                for (int q = 0; q < 16; q++) {
                    ulonglong2 rv = rr[q], hv = hh[q], wv;
                    wv = wir[q]; fma2(air, wv.x, rv.x); fma2(air, wv.y, rv.y);
                    wv = wiz[q]; fma2(aiz, wv.x, rv.x); fma2(aiz, wv.y, rv.y);
                    wv = win[q]; fma2(ain, wv.x, rv.x); fma2(ain, wv.y, rv.y);
                    wv = whr[q]; fma2(ahr, wv.x, hv.x); fma2(ahr, wv.y, hv.y);
                    wv = whz[q]; fma2(ahz, wv.x, hv.x); fma2(ahz, wv.y, hv.y);
                    wv = whn[q]; fma2(ahn, wv.x, hv.x); fma2(ahn, wv.y, hv.y);
                }
                float2 v;
                v = asf2(air); float ir  = v.x + v.y + sbih[j];
                v = asf2(aiz); float iz  = v.x + v.y + sbih[64 + j];
                v = asf2(ain); float inn = v.x + v.y + sbih[128 + j];
                v = asf2(ahr); float hr  = v.x + v.y + sbhh[j];
                v = asf2(ahz); float hz  = v.x + v.y + sbhh[64 + j];
                v = asf2(ahn); float hn  = v.x + v.y + sbhh[128 + j];
                float rg = fast_sigmoid(ir + hr);
                float zg = fast_sigmoid(iz + hz);
                float ng = fast_tanh(inn + rg * hn);
                float2 hjp = asf2((dj & 2) ? hh[jq].y : hh[jq].x);
                float hj = (dj & 1) ? hjp.y : hjp.x;
                float hnew = (1.f - zg) * ng + zg * hj;
                ull hn2;
                asm("mov.b64 %0, {%1, %1};" : "=l"(hn2) : "f"(hnew));
                const ulonglong2* wo = reinterpret_cast<const ulonglong2*>(sWoT + j * CC);
#pragma unroll
                for (int c = 0; c < 4; c++) {
                    ulonglong2 wv = wo[c];
                    fma2(oacc[2 * c], wv.x, hn2);
                    fma2(oacc[2 * c + 1], wv.y, hn2);
                }
            }
        }

        ulonglong2* op = reinterpret_cast<ulonglong2*>(out + (size_t)n * CC);
#pragma unroll
        for (int i = 0; i < 4; i++) {
            ulonglong2 v;
            v.x = oacc[2 * i]; v.y = oacc[2 * i + 1];
            op[i] = v;
        }
    }
}

// ---------------------------------------------------------------------------
extern "C" void kernel_launch(void* const* d_in, const int* in_sizes, int n_in,
                              void* d_out, int out_size) {
    const float* features = (const float*)d_in[0];
    const float* edge_emb = (const float*)d_in[1];
    const float* W_ih     = (const float*)d_in[2];
    const float* W_hh     = (const float*)d_in[3];
    const float* b_ih     = (const float*)d_in[4];
    const float* b_hh     = (const float*)d_in[5];
    const float* W_out    = (const float*)d_in[6];
    const float* b_out    = (const float*)d_in[7];
    const int*   etype    = (const int*)d_in[8];
    const int*   src      = (const int*)d_in[9];
    const int*   dst      = (const int*)d_in[10];
    float*       out      = (float*)d_out;

    cudaFuncSetAttribute(node_kernel, cudaFuncAttributeMaxDynamicSharedMemorySize, NODE_SMEM);

    zero_kernel<<<(NN * MSGD / 4 + 255) / 256, 256>>>();
    hist_kernel<<<(EE + 511) / 512, 512>>>(etype);
    scatter_kernel<<<(EE + 511) / 512, 512>>>(etype, src, dst);
    edge_kernel<<<EBLOCKS, ETHREADS>>>(features, edge_emb);
    node_kernel<<<NBLOCKS, NTHREADS, NODE_SMEM>>>(features, W_ih, W_hh,
                                                  b_ih, b_hh, W_out, b_out, out);
}

// round 9
// speedup vs baseline: 1.7551x; 1.7551x over previous
#include <cuda_runtime.h>
#include <math.h>

#define NN   100000
#define EE   500000
#define TT   8
#define MSGD 64
#define HIDD 64
#define CC   16

typedef unsigned long long ull;

// ---------------------------------------------------------------------------
// Device scratch
// ---------------------------------------------------------------------------
__device__ __align__(16) float g_reduced[(size_t)NN * MSGD];
__device__ __align__(16) float g_gi[(size_t)3 * HIDD * NN];   // [192][N] layout
__device__ int g_counts[TT];
__device__ int g_cursor[TT];
__device__ int g_src_s[EE];
__device__ int g_dst_s[EE];

// ---------------------------------------------------------------------------
// Packed fp32x2 helpers (Blackwell FFMA2)
// ---------------------------------------------------------------------------
__device__ __forceinline__ void fma2(ull& d, ull a, ull b) {
    asm volatile("fma.rn.f32x2 %0, %1, %2, %0;" : "+l"(d) : "l"(a), "l"(b));
}
__device__ __forceinline__ float2 asf2(ull v) {
    float2 r;
    asm("mov.b64 {%0, %1}, %2;" : "=f"(r.x), "=f"(r.y) : "l"(v));
    return r;
}
// Fast gate math (err ~1e-6, budget 1e-3). Saturates correctly at +/-inf.
__device__ __forceinline__ float fast_sigmoid(float x) {
    return __fdividef(1.f, 1.f + __expf(-x));
}
__device__ __forceinline__ float fast_tanh(float x) {
    return 1.f - __fdividef(2.f, __expf(2.f * x) + 1.f);
}

// ---------------------------------------------------------------------------
// Kernel 0: zero reduction buffer + reset counters (separate launch from
// histogram adds — launch boundary is the grid-wide ordering point).
// ---------------------------------------------------------------------------
__global__ void zero_kernel() {
    int i = blockIdx.x * blockDim.x + threadIdx.x;
    if (i < NN * MSGD / 4) {
        reinterpret_cast<float4*>(g_reduced)[i] = make_float4(0.f, 0.f, 0.f, 0.f);
    }
    if (blockIdx.x == 0 && threadIdx.x < TT) {
        g_counts[threadIdx.x] = 0;
        g_cursor[threadIdx.x] = 0;
    }
}

// ---------------------------------------------------------------------------
// Kernel 1: per-block histogram of edge types
// ---------------------------------------------------------------------------
__global__ void hist_kernel(const int* __restrict__ etype) {
    __shared__ int h[TT];
    if (threadIdx.x < TT) h[threadIdx.x] = 0;
    __syncthreads();
    int e = blockIdx.x * blockDim.x + threadIdx.x;
    if (e < EE) atomicAdd(&h[etype[e]], 1);
    __syncthreads();
    if (threadIdx.x < TT) atomicAdd(&g_counts[threadIdx.x], h[threadIdx.x]);
}

// ---------------------------------------------------------------------------
// Kernel 2: bin edges by type (bases from final g_counts via local prefix)
// ---------------------------------------------------------------------------
__global__ void scatter_kernel(const int* __restrict__ etype,
                               const int* __restrict__ src,
                               const int* __restrict__ dst) {
    __shared__ int h[TT], base[TT], h2[TT];
    int e = blockIdx.x * blockDim.x + threadIdx.x;
    if (threadIdx.x < TT) { h[threadIdx.x] = 0; h2[threadIdx.x] = 0; }
    __syncthreads();
    int t = 0, s = 0, d = 0;
    bool valid = (e < EE);
    if (valid) {
        t = etype[e]; s = src[e]; d = dst[e];
        atomicAdd(&h[t], 1);
    }
    __syncthreads();
    if (threadIdx.x < TT) {
        int b = 0;
#pragma unroll
        for (int q = 0; q < TT; q++) {
            int c = g_counts[q];
            if (q < (int)threadIdx.x) b += c;
        }
        base[threadIdx.x] = b + atomicAdd(&g_cursor[threadIdx.x], h[threadIdx.x]);
    }
    __syncthreads();
    if (valid) {
        int pos = base[t] + atomicAdd(&h2[t], 1);
        g_src_s[pos] = s;
        g_dst_s[pos] = d;
    }
}

// ---------------------------------------------------------------------------
// Kernel 3: edge messages — EXACT R4 WINNER (142.6us measured).
// One warp per edge stream; matrix in registers (2 rows/lane); cp.async ring
// depth 6; pair-lane red.v4 scatter (8M LTS atomic ops total).
// ---------------------------------------------------------------------------
#define EBLOCKS 148
#define ETHREADS 256
#define NWARP   (EBLOCKS * ETHREADS / 32)              // 1184
#define CHUNK   ((EE + NWARP - 1) / NWARP)             // 423

__global__ void __launch_bounds__(ETHREADS, 1)
edge_kernel(const float* __restrict__ features,
            const float* __restrict__ edge_emb) {
    __shared__ float4 sf[ETHREADS / 32][8][16];        // 8-slot ring per warp
    const unsigned FULL = 0xffffffffu;
    const int wib = threadIdx.x >> 5, lane = threadIdx.x & 31;

    int w = blockIdx.x * (ETHREADS / 32) + wib;
    long e0 = (long)w * CHUNK;
    if (e0 >= EE) return;
    long e1 = e0 + CHUNK;
    if (e1 > EE) e1 = EE;

    int bases[TT + 1];
    {
        int b = 0;
#pragma unroll
        for (int t = 0; t < TT; t++) { bases[t] = b; b += g_counts[t]; }
        bases[TT] = b;
    }

    ull wA[32], wB[32];  // rows 2*lane, 2*lane+1 of current type matrix
    long e = e0;
    int t = 0;
    while (e < e1) {
        while (bases[t + 1] <= e) t++;
        long seg_end = bases[t + 1] < e1 ? bases[t + 1] : e1;

        {
            const ulonglong2* pA = reinterpret_cast<const ulonglong2*>(
                edge_emb + (size_t)t * 4096 + (size_t)(2 * lane) * 64);
            const ulonglong2* pB = reinterpret_cast<const ulonglong2*>(
                edge_emb + (size_t)t * 4096 + (size_t)(2 * lane + 1) * 64);
#pragma unroll
            for (int q = 0; q < 16; q++) {
                ulonglong2 a = pA[q]; wA[2 * q] = a.x; wA[2 * q + 1] = a.y;
            }
#pragma unroll
            for (int q = 0; q < 16; q++) {
                ulonglong2 b = pB[q]; wB[2 * q] = b.x; wB[2 * q + 1] = b.y;
            }
        }

        for (long b0 = e; b0 < seg_end; b0 += 32) {
            int nb = (int)((seg_end - b0 < 32) ? (seg_end - b0) : 32);
            int my_s = 0, my_d = 0;
            if (lane < nb) {
                my_s = g_src_s[b0 + lane];
                my_d = g_dst_s[b0 + lane];
            }
            // Prologue: prefetch edges 0..5 (depth 6 of 8-slot ring)
#pragma unroll
            for (int j = 0; j < 6; j++) {
                if (j < nb) {
                    int s = __shfl_sync(FULL, my_s, j);
                    if (lane < 16) {
                        unsigned sp = (unsigned)__cvta_generic_to_shared(
                            &sf[wib][j & 7][lane]);
                        asm volatile("cp.async.cg.shared.global [%0], [%1], 16;"
                                     :: "r"(sp),
                                        "l"(features + (size_t)s * 64 + lane * 4));
                    }
                }
                asm volatile("cp.async.commit_group;");
            }
            for (int j = 0; j < nb; j++) {
                asm volatile("cp.async.wait_group 5;");
                __syncwarp();
                if (j + 6 < nb) {
                    int s = __shfl_sync(FULL, my_s, j + 6);
                    if (lane < 16) {
                        unsigned sp = (unsigned)__cvta_generic_to_shared(
                            &sf[wib][(j + 6) & 7][lane]);
                        asm volatile("cp.async.cg.shared.global [%0], [%1], 16;"
                                     :: "r"(sp),
                                        "l"(features + (size_t)s * 64 + lane * 4));
                    }
                }
                asm volatile("cp.async.commit_group;");

                int d = __shfl_sync(FULL, my_d, j);
                const ulonglong2* fp = reinterpret_cast<const ulonglong2*>(
                    &sf[wib][j & 7][0]);
                ull a0 = 0, a1 = 0, c0 = 0, c1 = 0;
#pragma unroll
                for (int q = 0; q < 16; q += 2) {
                    ulonglong2 f0 = fp[q], f1 = fp[q + 1];
                    fma2(a0, wA[2 * q],     f0.x); fma2(a0, wA[2 * q + 1], f0.y);
                    fma2(c0, wB[2 * q],     f0.x); fma2(c0, wB[2 * q + 1], f0.y);
                    fma2(a1, wA[2 * q + 2], f1.x); fma2(a1, wA[2 * q + 3], f1.y);
                    fma2(c1, wB[2 * q + 2], f1.x); fma2(c1, wB[2 * q + 3], f1.y);
                }
                float2 fa0 = asf2(a0), fa1 = asf2(a1);
                float2 fc0 = asf2(c0), fc1 = asf2(c1);
                float r0 = (fa0.x + fa0.y) + (fa1.x + fa1.y);   // dim 2*lane
                float r1 = (fc0.x + fc0.y) + (fc1.x + fc1.y);   // dim 2*lane+1
                float p0 = __shfl_xor_sync(FULL, r0, 1);
                float p1 = __shfl_xor_sync(FULL, r1, 1);
                if (!(lane & 1)) {
                    const float* op = g_reduced + (size_t)d * 64 + 2 * lane;
                    asm volatile("red.global.add.v4.f32 [%0], {%1, %2, %3, %4};"
                                 :: "l"(op), "f"(r0), "f"(r1), "f"(p0), "f"(p1)
                                 : "memory");
                }
            }
            asm volatile("cp.async.wait_group 0;");
            __syncwarp();
        }
        e = seg_end;
    }
}

// ---------------------------------------------------------------------------
// Kernel 4a: gi = reduced @ W_ih^T + b_ih, written to g_gi[192][N].
// Only rr (64 regs) of node state -> ~90 regs -> real 2 CTAs/SM, no spill.
// ---------------------------------------------------------------------------
#define GIA_SMEM ((12288 + 192) * 4)
#define NBLOCKS 296
#define NTHREADS 256
#define NODES_PER_BLOCK ((NN + NBLOCKS - 1) / NBLOCKS)   // 338

__global__ void __launch_bounds__(NTHREADS, 2)
gi_kernel(const float* __restrict__ W_ih, const float* __restrict__ b_ih) {
    extern __shared__ float sm[];
    float* sWih = sm;            // 192*64 = 12288
    float* sbih = sm + 12288;    // 192
    {
        float4* d1 = reinterpret_cast<float4*>(sWih);
        const float4* s1 = reinterpret_cast<const float4*>(W_ih);
        for (int i = threadIdx.x; i < 3072; i += blockDim.x) d1[i] = s1[i];
        for (int i = threadIdx.x; i < 192; i += blockDim.x) sbih[i] = b_ih[i];
    }
    __syncthreads();

    int nstart = blockIdx.x * NODES_PER_BLOCK;
    int nend   = nstart + NODES_PER_BLOCK;
    if (nend > NN) nend = NN;

    for (int n = nstart + threadIdx.x; n < nend; n += NTHREADS) {
        ulonglong2 rr[16];
        const ulonglong2* rp = reinterpret_cast<const ulonglong2*>(g_reduced + (size_t)n * 64);
#pragma unroll
        for (int q = 0; q < 16; q++) rr[q] = rp[q];

#pragma unroll 1
        for (int j = 0; j < 64; j++) {
            ull air = 0, aiz = 0, ain = 0;
            const ulonglong2* wir = reinterpret_cast<const ulonglong2*>(sWih + (j      ) * 64);
            const ulonglong2* wiz = reinterpret_cast<const ulonglong2*>(sWih + (64  + j) * 64);
            const ulonglong2* win = reinterpret_cast<const ulonglong2*>(sWih + (128 + j) * 64);
#pragma unroll
            for (int q = 0; q < 16; q++) {
                ulonglong2 rv = rr[q], wv;
                wv = wir[q]; fma2(air, wv.x, rv.x); fma2(air, wv.y, rv.y);
                wv = wiz[q]; fma2(aiz, wv.x, rv.x); fma2(aiz, wv.y, rv.y);
                wv = win[q]; fma2(ain, wv.x, rv.x); fma2(ain, wv.y, rv.y);
            }
            float2 v;
            v = asf2(air); float ir  = v.x + v.y + sbih[j];
            v = asf2(aiz); float iz  = v.x + v.y + sbih[64 + j];
            v = asf2(ain); float inn = v.x + v.y + sbih[128 + j];
            // [192][N] layout -> coalesced STG.32 across lanes
            g_gi[(size_t)(j      ) * NN + n] = ir;
            g_gi[(size_t)(64  + j) * NN + n] = iz;
            g_gi[(size_t)(128 + j) * NN + n] = inn;
        }
    }
}

// ---------------------------------------------------------------------------
// Kernel 4b: gh = features @ W_hh^T + b_hh; gates; out projection.
// Only hh (64 regs) of node state + 3 gi LDGs per j (coalesced, L2-resident).
// ---------------------------------------------------------------------------
#define GHB_SMEM ((12288 + 1024 + 192 + 16) * 4)

__global__ void __launch_bounds__(NTHREADS, 2)
gh_kernel(const float* __restrict__ features,
          const float* __restrict__ W_hh, const float* __restrict__ b_hh,
          const float* __restrict__ W_out, const float* __restrict__ b_out,
          float* __restrict__ out) {
    extern __shared__ float sm[];
    float* sWhh  = sm;            // 12288
    float* sWoT  = sm + 12288;    // 1024 (W_out transposed [64][16])
    float* sbhh  = sm + 13312;    // 192
    float* sbout = sm + 13504;    // 16
    {
        float4* d2 = reinterpret_cast<float4*>(sWhh);
        const float4* s2 = reinterpret_cast<const float4*>(W_hh);
        for (int i = threadIdx.x; i < 3072; i += blockDim.x) d2[i] = s2[i];
        for (int i = threadIdx.x; i < CC * 64; i += blockDim.x) {
            int c = i / 64, j = i % 64;
            sWoT[j * CC + c] = W_out[i];
        }
        for (int i = threadIdx.x; i < 192; i += blockDim.x) sbhh[i] = b_hh[i];
        if (threadIdx.x < CC) sbout[threadIdx.x] = b_out[threadIdx.x];
    }
    __syncthreads();

    int nstart = blockIdx.x * NODES_PER_BLOCK;
    int nend   = nstart + NODES_PER_BLOCK;
    if (nend > NN) nend = NN;

    for (int n = nstart + threadIdx.x; n < nend; n += NTHREADS) {
        ulonglong2 hh[16];
        const ulonglong2* hp = reinterpret_cast<const ulonglong2*>(features + (size_t)n * 64);
#pragma unroll
        for (int q = 0; q < 16; q++) hh[q] = hp[q];

        ull oacc[8];
        const ulonglong2* bo = reinterpret_cast<const ulonglong2*>(sbout);
#pragma unroll
        for (int i = 0; i < 4; i++) {
            ulonglong2 v = bo[i];
            oacc[2 * i] = v.x; oacc[2 * i + 1] = v.y;
        }

#pragma unroll 1
        for (int j = 0; j < 64; j++) {
            // Prefetch gi values early (L2-resident scratch)
            float ir  = __ldg(&g_gi[(size_t)(j      ) * NN + n]);
            float iz  = __ldg(&g_gi[(size_t)(64  + j) * NN + n]);
            float inn = __ldg(&g_gi[(size_t)(128 + j) * NN + n]);

            ull ahr = 0, ahz = 0, ahn = 0;
            const ulonglong2* whr = reinterpret_cast<const ulonglong2*>(sWhh + (j      ) * 64);
            const ulonglong2* whz = reinterpret_cast<const ulonglong2*>(sWhh + (64  + j) * 64);
            const ulonglong2* whn = reinterpret_cast<const ulonglong2*>(sWhh + (128 + j) * 64);
#pragma unroll
            for (int q = 0; q < 16; q++) {
                ulonglong2 hv = hh[q], wv;
                wv = whr[q]; fma2(ahr, wv.x, hv.x); fma2(ahr, wv.y, hv.y);
                wv = whz[q]; fma2(ahz, wv.x, hv.x); fma2(ahz, wv.y, hv.y);
                wv = whn[q]; fma2(ahn, wv.x, hv.x); fma2(ahn, wv.y, hv.y);
            }
            float2 v;
            v = asf2(ahr); float hr = v.x + v.y + sbhh[j];
            v = asf2(ahz); float hz = v.x + v.y + sbhh[64 + j];
            v = asf2(ahn); float hn = v.x + v.y + sbhh[128 + j];
            float rg = fast_sigmoid(ir + hr);
            float zg = fast_sigmoid(iz + hz);
            float ng = fast_tanh(inn + rg * hn);
            float2 hjp = asf2((j & 2) ? hh[j >> 2].y : hh[j >> 2].x);
            float hj = (j & 1) ? hjp.y : hjp.x;
            float hnew = (1.f - zg) * ng + zg * hj;
            ull hn2;
            asm("mov.b64 %0, {%1, %1};" : "=l"(hn2) : "f"(hnew));
            const ulonglong2* wo = reinterpret_cast<const ulonglong2*>(sWoT + j * CC);
#pragma unroll
            for (int c = 0; c < 4; c++) {
                ulonglong2 wv = wo[c];
                fma2(oacc[2 * c], wv.x, hn2);
                fma2(oacc[2 * c + 1], wv.y, hn2);
            }
        }

        ulonglong2* op = reinterpret_cast<ulonglong2*>(out + (size_t)n * CC);
#pragma unroll
        for (int i = 0; i < 4; i++) {
            ulonglong2 v;
            v.x = oacc[2 * i]; v.y = oacc[2 * i + 1];
            op[i] = v;
        }
    }
}

// ---------------------------------------------------------------------------
extern "C" void kernel_launch(void* const* d_in, const int* in_sizes, int n_in,
                              void* d_out, int out_size) {
    const float* features = (const float*)d_in[0];
    const float* edge_emb = (const float*)d_in[1];
    const float* W_ih     = (const float*)d_in[2];
    const float* W_hh     = (const float*)d_in[3];
    const float* b_ih     = (const float*)d_in[4];
    const float* b_hh     = (const float*)d_in[5];
    const float* W_out    = (const float*)d_in[6];
    const float* b_out    = (const float*)d_in[7];
    const int*   etype    = (const int*)d_in[8];
    const int*   src      = (const int*)d_in[9];
    const int*   dst      = (const int*)d_in[10];
    float*       out      = (float*)d_out;

    cudaFuncSetAttribute(gi_kernel, cudaFuncAttributeMaxDynamicSharedMemorySize, GIA_SMEM);
    cudaFuncSetAttribute(gh_kernel, cudaFuncAttributeMaxDynamicSharedMemorySize, GHB_SMEM);

    zero_kernel<<<(NN * MSGD / 4 + 255) / 256, 256>>>();
    hist_kernel<<<(EE + 511) / 512, 512>>>(etype);
    scatter_kernel<<<(EE + 511) / 512, 512>>>(etype, src, dst);
    edge_kernel<<<EBLOCKS, ETHREADS>>>(features, edge_emb);
    gi_kernel<<<NBLOCKS, NTHREADS, GIA_SMEM>>>(W_ih, b_ih);
    gh_kernel<<<NBLOCKS, NTHREADS, GHB_SMEM>>>(features, W_hh, b_hh,
                                               W_out, b_out, out);
}